// round 4
// baseline (speedup 1.0000x reference)
#include <cuda_runtime.h>
#include <math.h>

#define DET 512
#define NB  16
#define NT  180

// scratch: filtered sinogram, layout [b][t][d] (d contiguous).
// Two extra padding columns so prefetch of t+2/t+3 is always in-bounds.
static __device__ float g_xf[(size_t)NB * (NT + 2) * DET];

// ---------------------------------------------------------------------------
// Kernel 1: Ram-Lak filtering as direct convolution with closed-form kernel.
// ---------------------------------------------------------------------------
__global__ __launch_bounds__(512) void filter_kernel(const float* __restrict__ x)
{
    const int b  = blockIdx.x;
    const int t0 = blockIdx.y * 16;
    const int tid = threadIdx.x;            // 0..511

    __shared__ __align__(16) float xs[DET][16];   // x[b][m][t0..t0+15]
    __shared__ float Gt[DET];

    {
        int k = tid;
        float v;
        if (k == 0)       v = 0.5f;
        else if (k & 1) { float fk = (float)k; v = -2.0f / (9.869604401089358f * fk * fk); }
        else              v = 0.0f;
        Gt[k] = v;
    }

    const float* xb = x + (size_t)b * DET * NT;
    const int tt = tid & 15;
    const int mb = tid >> 4;                 // 0..31
    const int tg0 = t0 + tt;
    #pragma unroll
    for (int p = 0; p < 16; p++) {
        int m = mb + p * 32;
        xs[m][tt] = (tg0 < NT) ? xb[m * NT + tg0] : 0.0f;
    }
    __syncthreads();

    const int d = tid;
    float4 acc[4];
    {
        const float4* xd = (const float4*)xs[d];
        #pragma unroll
        for (int q = 0; q < 4; q++) {
            float4 v = xd[q];
            acc[q].x = 0.5f * v.x; acc[q].y = 0.5f * v.y;
            acc[q].z = 0.5f * v.z; acc[q].w = 0.5f * v.w;
        }
    }

    const int m0 = (d & 1) ^ 1;              // opposite parity of d
    for (int j = 0; j < 256; j++) {
        int m = m0 + 2 * j;
        int k = d - m; k = (k < 0) ? -k : k;
        float gv = Gt[k];
        const float4* xm = (const float4*)xs[m];
        #pragma unroll
        for (int q = 0; q < 4; q++) {
            float4 v = xm[q];
            acc[q].x = fmaf(gv, v.x, acc[q].x);
            acc[q].y = fmaf(gv, v.y, acc[q].y);
            acc[q].z = fmaf(gv, v.z, acc[q].z);
            acc[q].w = fmaf(gv, v.w, acc[q].w);
        }
    }

    float vals[16];
    #pragma unroll
    for (int q = 0; q < 4; q++) {
        vals[q*4+0] = acc[q].x; vals[q*4+1] = acc[q].y;
        vals[q*4+2] = acc[q].z; vals[q*4+3] = acc[q].w;
    }
    #pragma unroll
    for (int r = 0; r < 16; r++) {
        int tg = t0 + r;
        if (tg < NT) g_xf[((size_t)b * (NT + 2) + tg) * DET + d] = vals[r];
    }
}

// ---------------------------------------------------------------------------
// Kernel 2: backprojection. (g, delta) float2 columns, magic-number floor,
// independent per-tap FFMA address chains, 2 angles per barrier.
// ---------------------------------------------------------------------------
__device__ __forceinline__ void build_col(const float* __restrict__ src,
                                          float2* __restrict__ dst, int tid)
{
    float2 v = ((const float2*)src)[tid];
    float  e = (tid < 255) ? src[2 * tid + 2] : 0.0f;
    float4 pk = make_float4(v.x, v.y - v.x, v.y, e - v.y);
    ((float4*)(dst + 128))[tid] = pk;
    if (tid == 0) dst[127] = make_float2(0.0f, v.x);   // entry -1: (0, g0)
}

__global__ __launch_bounds__(256, 7) void backproj_kernel(float* __restrict__ out)
{
    const int b  = blockIdx.z;
    const int x0 = blockIdx.x * 64;
    const int y0 = blockIdx.y * 64;
    const int tid = threadIdx.x;             // 0..255
    const int tx = tid & 63;
    const int ty = tid >> 6;                 // 0..3

    // entry index range used: [22, 745); arrays cover [0, 768) = unpadded [-128, 640)
    __shared__ __align__(16) float2 col2[2][2][768];
    __shared__ float2 cs[NT];

    // zero all buffers (pads included); data regions rebuilt each phase
    #pragma unroll
    for (int i = tid; i < 768; i += 256) {
        col2[0][0][i] = make_float2(0.0f, 0.0f);
        col2[0][1][i] = make_float2(0.0f, 0.0f);
        col2[1][0][i] = make_float2(0.0f, 0.0f);
        col2[1][1][i] = make_float2(0.0f, 0.0f);
    }
    if (tid < NT) {
        float rad = (float)tid * 0.017453292519943295f;
        float sv, cv;
        sincosf(rad, &sv, &cv);
        cs[tid] = make_float2(cv, sv);
    }
    __syncthreads();

    const float* xfb = g_xf + (size_t)b * (NT + 2) * DET;

    build_col(xfb,        col2[0][0], tid);
    build_col(xfb + DET,  col2[0][1], tid);
    __syncthreads();

    float acc[16];
    #pragma unroll
    for (int k = 0; k < 16; k++) acc[k] = 0.0f;

    const float fx = (float)(x0 + tx) - 255.5f;
    const float fy = (float)(y0 + ty) - 255.5f;
    const float lim = 65408.0f;              // (1 - 1/512) * 256^2

    float fymin;
    {
        float lo = fy, hi = fy + 60.0f;
        fymin = (lo <= 0.0f && hi >= 0.0f) ? 0.0f : fminf(fabsf(lo), fabsf(hi));
    }
    const bool anyvalid = (fx * fx + fymin * fymin) <= lim;
    const bool warp_active = __any_sync(0xffffffffu, anyvalid);

    const float MAGIC = 8388608.0f;          // 2^23

    for (int t = 0; t < NT; t += 2) {
        const int cur = (t >> 1) & 1;
        const int nxt = cur ^ 1;
        // prefetch+build columns t+2, t+3 (pad columns exist past NT-1)
        build_col(xfb + (size_t)(t + 2) * DET, col2[nxt][0], tid);
        build_col(xfb + (size_t)(t + 3) * DET, col2[nxt][1], tid);

        if (warp_active) {
            #pragma unroll
            for (int a = 0; a < 2; a++) {
                const float c = cs[t + a].x, s = cs[t + a].y;
                // iy = c*(x-255.5) - s*(y-255.5) + 255.5, +128 pad offset
                const float iy0 = fmaf(c, fx, fmaf(-s, fy, 383.5f));
                const float s4 = 4.0f * s;
                const float2* cp = col2[cur][a];
                #pragma unroll
                for (int k = 0; k < 16; k++) {
                    float iyk = fmaf(-s4, (float)k, iy0);       // FFMA (imm)
                    float tmg = __fadd_rd(iyk, MAGIC);          // 2^23 + floor(iyk)
                    int   i0  = __float_as_int(tmg) & 0x3FF;    // floor as int
                    float fl  = tmg - MAGIC;                    // floor as float
                    float w   = iyk - fl;
                    float2 gd = cp[i0];
                    acc[k] = fmaf(w, gd.y, acc[k] + gd.x);
                }
            }
        }
        __syncthreads();
    }

    // epilogue: circle mask + pi/(2*180) scale
    const float scale = 0.008726646259971648f;   // pi/360
    float* ob = out + (size_t)b * DET * DET;
    #pragma unroll
    for (int k = 0; k < 16; k++) {
        int   py  = y0 + ty + 4 * k;
        float fyk = fy + 4.0f * (float)k;
        float m   = ((fx * fx + fyk * fyk) <= lim) ? 1.0f : 0.0f;
        ob[(size_t)py * DET + (x0 + tx)] = acc[k] * m * scale;
    }
}

extern "C" void kernel_launch(void* const* d_in, const int* in_sizes, int n_in,
                              void* d_out, int out_size)
{
    const float* x = (const float*)d_in[0];
    float* out = (float*)d_out;

    dim3 gf(NB, 12);          // 16 batches x ceil(180/16) angle tiles
    filter_kernel<<<gf, 512>>>(x);

    dim3 gb(8, 8, NB);        // 8x8 tiles of 64x64 pixels, per batch
    backproj_kernel<<<gb, 256>>>(out);
}

// round 5
// speedup vs baseline: 1.0028x; 1.0028x over previous
#include <cuda_runtime.h>
#include <math.h>

#define DET 512
#define NB  16
#define NT  180

// scratch: filtered sinogram, layout [b][t][d] (d contiguous).
// Two extra padding columns so prefetch of t+2/t+3 is always in-bounds.
static __device__ float g_xf[(size_t)NB * (NT + 2) * DET];

// ---------------------------------------------------------------------------
// Kernel 1: Ram-Lak filtering as direct convolution with closed-form kernel.
// ---------------------------------------------------------------------------
__global__ __launch_bounds__(512) void filter_kernel(const float* __restrict__ x)
{
    const int b  = blockIdx.x;
    const int t0 = blockIdx.y * 16;
    const int tid = threadIdx.x;            // 0..511

    __shared__ __align__(16) float xs[DET][16];   // x[b][m][t0..t0+15]
    __shared__ float Gt[DET];

    {
        int k = tid;
        float v;
        if (k == 0)       v = 0.5f;
        else if (k & 1) { float fk = (float)k; v = -2.0f / (9.869604401089358f * fk * fk); }
        else              v = 0.0f;
        Gt[k] = v;
    }

    const float* xb = x + (size_t)b * DET * NT;
    const int tt = tid & 15;
    const int mb = tid >> 4;                 // 0..31
    const int tg0 = t0 + tt;
    #pragma unroll
    for (int p = 0; p < 16; p++) {
        int m = mb + p * 32;
        xs[m][tt] = (tg0 < NT) ? xb[m * NT + tg0] : 0.0f;
    }
    __syncthreads();

    const int d = tid;
    float4 acc[4];
    {
        const float4* xd = (const float4*)xs[d];
        #pragma unroll
        for (int q = 0; q < 4; q++) {
            float4 v = xd[q];
            acc[q].x = 0.5f * v.x; acc[q].y = 0.5f * v.y;
            acc[q].z = 0.5f * v.z; acc[q].w = 0.5f * v.w;
        }
    }

    const int m0 = (d & 1) ^ 1;              // opposite parity of d
    for (int j = 0; j < 256; j++) {
        int m = m0 + 2 * j;
        int k = d - m; k = (k < 0) ? -k : k;
        float gv = Gt[k];
        const float4* xm = (const float4*)xs[m];
        #pragma unroll
        for (int q = 0; q < 4; q++) {
            float4 v = xm[q];
            acc[q].x = fmaf(gv, v.x, acc[q].x);
            acc[q].y = fmaf(gv, v.y, acc[q].y);
            acc[q].z = fmaf(gv, v.z, acc[q].z);
            acc[q].w = fmaf(gv, v.w, acc[q].w);
        }
    }

    float vals[16];
    #pragma unroll
    for (int q = 0; q < 4; q++) {
        vals[q*4+0] = acc[q].x; vals[q*4+1] = acc[q].y;
        vals[q*4+2] = acc[q].z; vals[q*4+3] = acc[q].w;
    }
    #pragma unroll
    for (int r = 0; r < 16; r++) {
        int tg = t0 + r;
        if (tg < NT) g_xf[((size_t)b * (NT + 2) + tg) * DET + d] = vals[r];
    }
}

// ---------------------------------------------------------------------------
// Kernel 2: backprojection. 64x128 tile, 512 threads, 16 px/thread
// (y-strided by 8). (g, delta) float2 columns, magic floor, independent
// per-tap FFMA chains, 2 angles per barrier, 100%-occ launch bounds.
// ---------------------------------------------------------------------------
__device__ __forceinline__ void build_col(const float* __restrict__ src,
                                          float2* __restrict__ dst, int tid)
{
    // one entry per thread: dst[128+i] = (g_i, g_{i+1} - g_i)
    float a = src[tid];
    float bnext = (tid < DET - 1) ? src[tid + 1] : 0.0f;
    dst[128 + tid] = make_float2(a, bnext - a);
    if (tid == 0) dst[127] = make_float2(0.0f, a);   // entry -1: (0, g0)
}

__global__ __launch_bounds__(512, 4) void backproj_kernel(float* __restrict__ out)
{
    const int b  = blockIdx.z;
    const int x0 = blockIdx.x * 64;
    const int y0 = blockIdx.y * 128;
    const int tid = threadIdx.x;             // 0..511
    const int tx = tid & 63;
    const int ty = tid >> 6;                 // 0..7

    // entry index range used: [22, 746); arrays cover [0, 768) = unpadded [-128, 640)
    __shared__ __align__(16) float2 col2[2][2][768];
    __shared__ float2 cs[NT];

    // zero all buffers (pads included); data regions rebuilt each phase
    #pragma unroll
    for (int i = tid; i < 768; i += 512) {
        col2[0][0][i] = make_float2(0.0f, 0.0f);
        col2[0][1][i] = make_float2(0.0f, 0.0f);
        col2[1][0][i] = make_float2(0.0f, 0.0f);
        col2[1][1][i] = make_float2(0.0f, 0.0f);
    }
    if (tid < NT) {
        float rad = (float)tid * 0.017453292519943295f;
        float sv, cv;
        sincosf(rad, &sv, &cv);
        cs[tid] = make_float2(cv, sv);
    }
    __syncthreads();

    const float* xfb = g_xf + (size_t)b * (NT + 2) * DET;

    build_col(xfb,        col2[0][0], tid);
    build_col(xfb + DET,  col2[0][1], tid);
    __syncthreads();

    float acc[16];
    #pragma unroll
    for (int k = 0; k < 16; k++) acc[k] = 0.0f;

    const float fx = (float)(x0 + tx) - 255.5f;
    const float fy = (float)(y0 + ty) - 255.5f;
    const float lim = 65408.0f;              // (1 - 1/512) * 256^2

    // does any of this thread's 16 pixels (fy + 8k, k<16) lie inside?
    float fymin;
    {
        float lo = fy, hi = fy + 120.0f;
        fymin = (lo <= 0.0f && hi >= 0.0f) ? 0.0f : fminf(fabsf(lo), fabsf(hi));
    }
    const bool anyvalid = (fx * fx + fymin * fymin) <= lim;
    const bool warp_active = __any_sync(0xffffffffu, anyvalid);

    const float MAGIC = 8388608.0f;          // 2^23

    for (int t = 0; t < NT; t += 2) {
        const int cur = (t >> 1) & 1;
        const int nxt = cur ^ 1;
        // prefetch+build columns t+2, t+3 (pad columns exist past NT-1)
        build_col(xfb + (size_t)(t + 2) * DET, col2[nxt][0], tid);
        build_col(xfb + (size_t)(t + 3) * DET, col2[nxt][1], tid);

        if (warp_active) {
            #pragma unroll
            for (int a = 0; a < 2; a++) {
                const float c = cs[t + a].x, s = cs[t + a].y;
                // iy = c*(x-255.5) - s*(y-255.5) + 255.5, +128 pad offset
                const float iy0 = fmaf(c, fx, fmaf(-s, fy, 383.5f));
                const float s8 = 8.0f * s;
                const float2* cp = col2[cur][a];
                #pragma unroll
                for (int k = 0; k < 16; k++) {
                    float iyk = fmaf(-s8, (float)k, iy0);       // FFMA (imm)
                    float tmg = __fadd_rd(iyk, MAGIC);          // 2^23 + floor(iyk)
                    int   i0  = __float_as_int(tmg) & 0x3FF;    // floor as int
                    float fl  = tmg - MAGIC;                    // floor as float
                    float w   = iyk - fl;
                    float2 gd = cp[i0];
                    acc[k] = fmaf(w, gd.y, acc[k] + gd.x);
                }
            }
        }
        __syncthreads();
    }

    // epilogue: circle mask + pi/(2*180) scale
    const float scale = 0.008726646259971648f;   // pi/360
    float* ob = out + (size_t)b * DET * DET;
    #pragma unroll
    for (int k = 0; k < 16; k++) {
        int   py  = y0 + ty + 8 * k;
        float fyk = fy + 8.0f * (float)k;
        float m   = ((fx * fx + fyk * fyk) <= lim) ? 1.0f : 0.0f;
        ob[(size_t)py * DET + (x0 + tx)] = acc[k] * m * scale;
    }
}

extern "C" void kernel_launch(void* const* d_in, const int* in_sizes, int n_in,
                              void* d_out, int out_size)
{
    const float* x = (const float*)d_in[0];
    float* out = (float*)d_out;

    dim3 gf(NB, 12);          // 16 batches x ceil(180/16) angle tiles
    filter_kernel<<<gf, 512>>>(x);

    dim3 gb(8, 4, NB);        // 8x4 tiles of 64x128 pixels, per batch
    backproj_kernel<<<gb, 512>>>(out);
}

// round 6
// speedup vs baseline: 1.0790x; 1.0760x over previous
#include <cuda_runtime.h>
#include <math.h>

#define DET 512
#define NB  16
#define NT  180

// scratch: filtered sinogram, layout [b][t][d] (d contiguous)
static __device__ float g_xf[(size_t)NB * NT * DET];

// ---------------------------------------------------------------------------
// Kernel 1: Ram-Lak filtering as direct convolution with closed-form kernel.
// ---------------------------------------------------------------------------
__global__ __launch_bounds__(512) void filter_kernel(const float* __restrict__ x)
{
    const int b  = blockIdx.x;
    const int t0 = blockIdx.y * 16;
    const int tid = threadIdx.x;            // 0..511

    __shared__ __align__(16) float xs[DET][16];   // x[b][m][t0..t0+15]
    __shared__ float Gt[DET];

    {
        int k = tid;
        float v;
        if (k == 0)       v = 0.5f;
        else if (k & 1) { float fk = (float)k; v = -2.0f / (9.869604401089358f * fk * fk); }
        else              v = 0.0f;
        Gt[k] = v;
    }

    const float* xb = x + (size_t)b * DET * NT;
    const int tt = tid & 15;
    const int mb = tid >> 4;                 // 0..31
    const int tg0 = t0 + tt;
    #pragma unroll
    for (int p = 0; p < 16; p++) {
        int m = mb + p * 32;
        xs[m][tt] = (tg0 < NT) ? xb[m * NT + tg0] : 0.0f;
    }
    __syncthreads();

    const int d = tid;
    float4 acc[4];
    {
        const float4* xd = (const float4*)xs[d];
        #pragma unroll
        for (int q = 0; q < 4; q++) {
            float4 v = xd[q];
            acc[q].x = 0.5f * v.x; acc[q].y = 0.5f * v.y;
            acc[q].z = 0.5f * v.z; acc[q].w = 0.5f * v.w;
        }
    }

    const int m0 = (d & 1) ^ 1;              // opposite parity of d
    for (int j = 0; j < 256; j++) {
        int m = m0 + 2 * j;
        int k = d - m; k = (k < 0) ? -k : k;
        float gv = Gt[k];
        const float4* xm = (const float4*)xs[m];
        #pragma unroll
        for (int q = 0; q < 4; q++) {
            float4 v = xm[q];
            acc[q].x = fmaf(gv, v.x, acc[q].x);
            acc[q].y = fmaf(gv, v.y, acc[q].y);
            acc[q].z = fmaf(gv, v.z, acc[q].z);
            acc[q].w = fmaf(gv, v.w, acc[q].w);
        }
    }

    float vals[16];
    #pragma unroll
    for (int q = 0; q < 4; q++) {
        vals[q*4+0] = acc[q].x; vals[q*4+1] = acc[q].y;
        vals[q*4+2] = acc[q].z; vals[q*4+3] = acc[q].w;
    }
    #pragma unroll
    for (int r = 0; r < 16; r++) {
        int tg = t0 + r;
        if (tg < NT) g_xf[((size_t)b * NT + tg) * DET + d] = vals[r];
    }
}

// ---------------------------------------------------------------------------
// Kernel 2: backprojection with mirror-angle pairing.
// Each thread owns pixel (x, y..) AND its mirror (511-x, y..), 8 y's each.
// Angle pair (t, 180-t): the 4 taps (2 px x 2 angles) need only 2 detector
// indices; columns for both angles interleaved as float4 (g_t, d_t, g_u, d_u)
// so one LDS.128 feeds two taps.
// ---------------------------------------------------------------------------
__device__ __forceinline__ void build_col4(const float* __restrict__ st,
                                           const float* __restrict__ su,
                                           float4* __restrict__ dst, int tid)
{
    #pragma unroll
    for (int r = 0; r < 2; r++) {
        int i = tid + r * 256;
        float a  = st[i];
        float b  = (i < DET - 1) ? st[i + 1] : 0.0f;
        float c  = su[i];
        float d2 = (i < DET - 1) ? su[i + 1] : 0.0f;
        dst[128 + i] = make_float4(a, b - a, c, d2 - c);
    }
    if (tid == 0) dst[127] = make_float4(0.0f, st[0], 0.0f, su[0]);  // entry -1
}

#define TAPLOOKUP(cp, iy, q, w)                              \
    {   float _tm = __fadd_rd((iy), MAGIC);                  \
        int   _ii = __float_as_int(_tm) & 0x3FF;             \
        (w) = (iy) - (_tm - MAGIC);                          \
        (q) = (cp)[_ii]; }

__global__ __launch_bounds__(256, 7) void backproj_kernel(float* __restrict__ out)
{
    const int b  = blockIdx.z;
    const int x0 = blockIdx.x * 32;          // left-half x tile [x0, x0+32)
    const int y0 = blockIdx.y * 64;          // y tile [y0, y0+64)
    const int tid = threadIdx.x;             // 0..255
    const int tx = tid & 31;
    const int ty = tid >> 5;                 // 0..7

    // padded index space [0,768) = detector [-128, 640); used range [22,745)
    __shared__ __align__(16) float4 col4[2][768];
    __shared__ float2 cs[NT];

    #pragma unroll
    for (int i = tid; i < 768; i += 256) {
        col4[0][i] = make_float4(0.0f, 0.0f, 0.0f, 0.0f);
        col4[1][i] = make_float4(0.0f, 0.0f, 0.0f, 0.0f);
    }
    if (tid < NT) {
        float rad = (float)tid * 0.017453292519943295f;
        float sv, cv;
        sincosf(rad, &sv, &cv);
        cs[tid] = make_float2(cv, sv);
    }
    __syncthreads();

    const float* xfb = g_xf + (size_t)b * NT * DET;

    // phase 0 = angles {0, 90}
    build_col4(xfb, xfb + 90 * DET, col4[0], tid);
    __syncthreads();

    float accP1[8], accP2[8];
    #pragma unroll
    for (int k = 0; k < 8; k++) { accP1[k] = 0.0f; accP2[k] = 0.0f; }

    const float fx = (float)(x0 + tx) - 255.5f;        // < 0 always
    const float fy = (float)(y0 + ty) - 255.5f;
    const float lim = 65408.0f;                        // (1 - 1/512) * 256^2
    const float MAGIC = 8388608.0f;                    // 2^23

    // warp-uniform skip: min |fx| over warp (all lanes same x-strip) and
    // min |fy| over this thread's 8 y's (stride 8, span 56)
    const float fxmin = 255.5f - (float)(x0 + 31);
    float fymin;
    {
        float lo = fy, hi = fy + 56.0f;
        fymin = (lo <= 0.0f && hi >= 0.0f) ? 0.0f : fminf(fabsf(lo), fabsf(hi));
    }
    const bool active = (fxmin * fxmin + fymin * fymin) <= lim;  // warp-uniform

    for (int ph = 0; ph < 90; ph++) {
        const int cur = ph & 1;
        // prefetch next phase's columns (ph=89 prefetches (90,90): valid, unused)
        build_col4(xfb + (size_t)(ph + 1) * DET,
                   xfb + (size_t)(179 - ph) * DET, col4[cur ^ 1], tid);

        if (active) {
            const float4* cp = col4[cur];
            if (ph == 0) {
                // special: angles 0 (lo half) and 90 (hi half), independent taps
                const float2 a0 = cs[0];
                const float2 a9 = cs[90];
                #pragma unroll
                for (int k = 0; k < 8; k++) {
                    float fyk = fy + 8.0f * (float)k;
                    float b0 = fmaf(-a0.y, fyk, 383.5f);
                    float b9 = fmaf(-a9.y, fyk, 383.5f);
                    float iy, w; float4 q;
                    iy = fmaf(a0.x,  fx, b0); TAPLOOKUP(cp, iy, q, w);
                    accP1[k] = fmaf(w, q.y, accP1[k] + q.x);
                    iy = fmaf(a0.x, -fx, b0); TAPLOOKUP(cp, iy, q, w);
                    accP2[k] = fmaf(w, q.y, accP2[k] + q.x);
                    iy = fmaf(a9.x,  fx, b9); TAPLOOKUP(cp, iy, q, w);
                    accP1[k] = fmaf(w, q.w, accP1[k] + q.z);
                    iy = fmaf(a9.x, -fx, b9); TAPLOOKUP(cp, iy, q, w);
                    accP2[k] = fmaf(w, q.w, accP2[k] + q.z);
                }
            } else {
                // pair (t=ph, u=180-ph): c_u = -c, s_u = s
                const float2 cst = cs[ph];
                const float c = cst.x, s = cst.y;
                const float iyA0 = fmaf(c, fx, fmaf(-s, fy, 383.5f));
                const float D    = -2.0f * (c * fx);      // iyB = iyA + D
                const float s8   = 8.0f * s;
                #pragma unroll
                for (int k = 0; k < 8; k++) {
                    float iyA = fmaf(-s8, (float)k, iyA0);
                    float w; float4 q;
                    TAPLOOKUP(cp, iyA, q, w);
                    accP1[k] = fmaf(w, q.y, accP1[k] + q.x);  // (p1, t)
                    accP2[k] = fmaf(w, q.w, accP2[k] + q.z);  // (p2, u)
                    float iyB = iyA + D;
                    TAPLOOKUP(cp, iyB, q, w);
                    accP1[k] = fmaf(w, q.w, accP1[k] + q.z);  // (p1, u)
                    accP2[k] = fmaf(w, q.y, accP2[k] + q.x);  // (p2, t)
                }
            }
        }
        __syncthreads();
    }

    // epilogue: circle mask (mirror-exact) + pi/(2*180) scale
    const float scale = 0.008726646259971648f;   // pi/360
    float* ob = out + (size_t)b * DET * DET;
    const int x1 = x0 + tx;
    const int x2 = 511 - x1;
    #pragma unroll
    for (int k = 0; k < 8; k++) {
        int   py  = y0 + ty + 8 * k;
        float fyk = fy + 8.0f * (float)k;
        float m   = ((fx * fx + fyk * fyk) <= lim) ? scale : 0.0f;
        ob[(size_t)py * DET + x1] = accP1[k] * m;
        ob[(size_t)py * DET + x2] = accP2[k] * m;
    }
}

extern "C" void kernel_launch(void* const* d_in, const int* in_sizes, int n_in,
                              void* d_out, int out_size)
{
    const float* x = (const float*)d_in[0];
    float* out = (float*)d_out;

    dim3 gf(NB, 12);          // 16 batches x ceil(180/16) angle tiles
    filter_kernel<<<gf, 512>>>(x);

    dim3 gb(8, 8, NB);        // 8 x-tiles (left half, mirrored) x 8 y-tiles
    backproj_kernel<<<gb, 256>>>(out);
}

// round 9
// speedup vs baseline: 1.2103x; 1.1217x over previous
#include <cuda_runtime.h>
#include <cuda_fp16.h>
#include <math.h>

#define DET 512
#define NB  16
#define NT  180
#define NPH 90
#define CW  768   // padded column width: detector index range [-128, 640)

// filtered sinogram, layout [b][t][d]
static __device__ float g_xf[(size_t)NB * NT * DET];
// packed pair-columns: [b][ph][i] = (half2(g_t,d_t), half2(g_u,d_u)), i in [0,768)
static __device__ uint2 g_pk[(size_t)NB * NPH * CW];

// bit-cast helpers (register moves only)
__device__ __forceinline__ unsigned int h2_to_u32(__half2 h) {
    return *reinterpret_cast<unsigned int*>(&h);
}
__device__ __forceinline__ __half2 u32_to_h2(unsigned int u) {
    return *reinterpret_cast<__half2*>(&u);
}

// ---------------------------------------------------------------------------
// Kernel 1: Ram-Lak filtering as direct convolution with closed-form kernel.
// ---------------------------------------------------------------------------
__global__ __launch_bounds__(512) void filter_kernel(const float* __restrict__ x)
{
    const int b  = blockIdx.x;
    const int t0 = blockIdx.y * 16;
    const int tid = threadIdx.x;            // 0..511

    __shared__ __align__(16) float xs[DET][16];   // x[b][m][t0..t0+15]
    __shared__ float Gt[DET];

    {
        int k = tid;
        float v;
        if (k == 0)       v = 0.5f;
        else if (k & 1) { float fk = (float)k; v = -2.0f / (9.869604401089358f * fk * fk); }
        else              v = 0.0f;
        Gt[k] = v;
    }

    const float* xb = x + (size_t)b * DET * NT;
    const int tt = tid & 15;
    const int mb = tid >> 4;                 // 0..31
    const int tg0 = t0 + tt;
    #pragma unroll
    for (int p = 0; p < 16; p++) {
        int m = mb + p * 32;
        xs[m][tt] = (tg0 < NT) ? xb[m * NT + tg0] : 0.0f;
    }
    __syncthreads();

    const int d = tid;
    float4 acc[4];
    {
        const float4* xd = (const float4*)xs[d];
        #pragma unroll
        for (int q = 0; q < 4; q++) {
            float4 v = xd[q];
            acc[q].x = 0.5f * v.x; acc[q].y = 0.5f * v.y;
            acc[q].z = 0.5f * v.z; acc[q].w = 0.5f * v.w;
        }
    }

    const int m0 = (d & 1) ^ 1;              // opposite parity of d
    for (int j = 0; j < 256; j++) {
        int m = m0 + 2 * j;
        int k = d - m; k = (k < 0) ? -k : k;
        float gv = Gt[k];
        const float4* xm = (const float4*)xs[m];
        #pragma unroll
        for (int q = 0; q < 4; q++) {
            float4 v = xm[q];
            acc[q].x = fmaf(gv, v.x, acc[q].x);
            acc[q].y = fmaf(gv, v.y, acc[q].y);
            acc[q].z = fmaf(gv, v.z, acc[q].z);
            acc[q].w = fmaf(gv, v.w, acc[q].w);
        }
    }

    float vals[16];
    #pragma unroll
    for (int q = 0; q < 4; q++) {
        vals[q*4+0] = acc[q].x; vals[q*4+1] = acc[q].y;
        vals[q*4+2] = acc[q].z; vals[q*4+3] = acc[q].w;
    }
    #pragma unroll
    for (int r = 0; r < 16; r++) {
        int tg = t0 + r;
        if (tg < NT) g_xf[((size_t)b * NT + tg) * DET + d] = vals[r];
    }
}

// ---------------------------------------------------------------------------
// Kernel 1b: repack into padded, fp16-packed pair-columns.
// ph=0 -> angles {0, 90}; ph in 1..89 -> angles {ph, 180-ph}.
// Entry i covers detector index d = i-128. Pads are zero; d=-1 is (0, g0)
// and d=511 is (g511, -g511), reproducing exact reference edge masking.
// ---------------------------------------------------------------------------
__global__ __launch_bounds__(256) void repack_kernel()
{
    const int b  = blockIdx.x;
    const int ph = blockIdx.y;
    const int t = (ph == 0) ? 0  : ph;
    const int u = (ph == 0) ? 90 : (180 - ph);   // FIXED: was 179-ph (off by one)

    const float* st = g_xf + ((size_t)b * NT + t) * DET;
    const float* su = g_xf + ((size_t)b * NT + u) * DET;
    uint2* dst = g_pk + ((size_t)b * NPH + ph) * CW;

    for (int i = threadIdx.x; i < CW; i += 256) {
        int d = i - 128;
        float gt = 0.0f, dt = 0.0f, gu = 0.0f, du = 0.0f;
        if (d >= 0 && d < DET) {
            gt = st[d]; dt = ((d < DET - 1) ? st[d + 1] : 0.0f) - gt;
            gu = su[d]; du = ((d < DET - 1) ? su[d + 1] : 0.0f) - gu;
        } else if (d == -1) {
            dt = st[0]; du = su[0];
        }
        uint2 e;
        e.x = h2_to_u32(__floats2half2_rn(gt, dt));
        e.y = h2_to_u32(__floats2half2_rn(gu, du));
        dst[i] = e;
    }
}

// ---------------------------------------------------------------------------
// Kernel 2: backprojection, mirror-angle pairing, fp16 packed columns.
// One LDS.64 per detector index feeds 2 taps (both angles of the pair).
// ---------------------------------------------------------------------------
#define TAPIDX(iy, i0, w)                                    \
    {   float _tm = __fadd_rd((iy), MAGIC);                  \
        (i0) = __float_as_int(_tm) & 0x3FF;                  \
        (w)  = (iy) - (_tm - MAGIC); }

__global__ __launch_bounds__(256, 7) void backproj_kernel(float* __restrict__ out)
{
    const int b  = blockIdx.z;
    const int x0 = blockIdx.x * 32;          // left-half x tile [x0, x0+32)
    const int y0 = blockIdx.y * 64;          // y tile [y0, y0+64)
    const int tid = threadIdx.x;             // 0..255
    const int tx = tid & 31;
    const int ty = tid >> 5;                 // 0..7

    __shared__ __align__(16) uint2 col[2][CW];
    __shared__ float2 cs[NT];

    if (tid < NT) {
        float rad = (float)tid * 0.017453292519943295f;
        float sv, cv;
        sincosf(rad, &sv, &cv);
        cs[tid] = make_float2(cv, sv);
    }

    const uint2* pkb = g_pk + (size_t)b * NPH * CW;

    // preload phase 0
    #pragma unroll
    for (int r = 0; r < 3; r++) col[0][tid + r * 256] = pkb[tid + r * 256];
    __syncthreads();

    float accP1[8], accP2[8];
    #pragma unroll
    for (int k = 0; k < 8; k++) { accP1[k] = 0.0f; accP2[k] = 0.0f; }

    const float fx = (float)(x0 + tx) - 255.5f;        // < 0 always
    const float fy = (float)(y0 + ty) - 255.5f;
    const float lim = 65408.0f;                        // (1 - 1/512) * 256^2
    const float MAGIC = 8388608.0f;                    // 2^23

    const float fxmin = 255.5f - (float)(x0 + 31);
    float fymin;
    {
        float lo = fy, hi = fy + 56.0f;
        fymin = (lo <= 0.0f && hi >= 0.0f) ? 0.0f : fminf(fabsf(lo), fabsf(hi));
    }
    const bool active = (fxmin * fxmin + fymin * fymin) <= lim;  // warp-uniform

    for (int ph = 0; ph < NPH; ph++) {
        const int cur = ph & 1;
        // prefetch next phase (ph=89 re-reads phase 89: valid, unused)
        {
            const uint2* src = pkb + (size_t)((ph + 1 < NPH) ? ph + 1 : ph) * CW;
            uint2* dstc = col[cur ^ 1];
            #pragma unroll
            for (int r = 0; r < 3; r++) dstc[tid + r * 256] = src[tid + r * 256];
        }

        if (active) {
            const uint2* cp = col[cur];
            if (ph == 0) {
                // angles 0 (.x half) and 90 (.y half): 4 independent lookups
                const float2 a0 = cs[0];
                const float2 a9 = cs[90];
                #pragma unroll
                for (int k = 0; k < 8; k++) {
                    float fyk = fy + 8.0f * (float)k;
                    float b0 = fmaf(-a0.y, fyk, 383.5f);
                    float b9 = fmaf(-a9.y, fyk, 383.5f);
                    float iy, w; int i0; uint2 q; float2 gd;
                    iy = fmaf(a0.x,  fx, b0); TAPIDX(iy, i0, w); q = cp[i0];
                    gd = __half22float2(u32_to_h2(q.x));
                    accP1[k] = fmaf(w, gd.y, accP1[k] + gd.x);
                    iy = fmaf(a0.x, -fx, b0); TAPIDX(iy, i0, w); q = cp[i0];
                    gd = __half22float2(u32_to_h2(q.x));
                    accP2[k] = fmaf(w, gd.y, accP2[k] + gd.x);
                    iy = fmaf(a9.x,  fx, b9); TAPIDX(iy, i0, w); q = cp[i0];
                    gd = __half22float2(u32_to_h2(q.y));
                    accP1[k] = fmaf(w, gd.y, accP1[k] + gd.x);
                    iy = fmaf(a9.x, -fx, b9); TAPIDX(iy, i0, w); q = cp[i0];
                    gd = __half22float2(u32_to_h2(q.y));
                    accP2[k] = fmaf(w, gd.y, accP2[k] + gd.x);
                }
            } else {
                // pair (t=ph, u=180-ph): c_u = -c, s_u = s
                const float2 cst = cs[ph];
                const float c = cst.x, s = cst.y;
                const float iyA0 = fmaf(c, fx, fmaf(-s, fy, 383.5f));
                const float D    = -2.0f * (c * fx);      // iyB = iyA + D
                const float s8   = 8.0f * s;
                #pragma unroll
                for (int k = 0; k < 8; k++) {
                    float iyA = fmaf(-s8, (float)k, iyA0);
                    float w; int i0; uint2 q; float2 gd;
                    TAPIDX(iyA, i0, w); q = cp[i0];
                    gd = __half22float2(u32_to_h2(q.x));
                    accP1[k] = fmaf(w, gd.y, accP1[k] + gd.x);   // (p1, t)
                    gd = __half22float2(u32_to_h2(q.y));
                    accP2[k] = fmaf(w, gd.y, accP2[k] + gd.x);   // (p2, u)
                    float iyB = iyA + D;
                    TAPIDX(iyB, i0, w); q = cp[i0];
                    gd = __half22float2(u32_to_h2(q.y));
                    accP1[k] = fmaf(w, gd.y, accP1[k] + gd.x);   // (p1, u)
                    gd = __half22float2(u32_to_h2(q.x));
                    accP2[k] = fmaf(w, gd.y, accP2[k] + gd.x);   // (p2, t)
                }
            }
        }
        __syncthreads();
    }

    // epilogue: circle mask (mirror-exact) + pi/(2*180) scale
    const float scale = 0.008726646259971648f;   // pi/360
    float* ob = out + (size_t)b * DET * DET;
    const int x1 = x0 + tx;
    const int x2 = 511 - x1;
    #pragma unroll
    for (int k = 0; k < 8; k++) {
        int   py  = y0 + ty + 8 * k;
        float fyk = fy + 8.0f * (float)k;
        float m   = ((fx * fx + fyk * fyk) <= lim) ? scale : 0.0f;
        ob[(size_t)py * DET + x1] = accP1[k] * m;
        ob[(size_t)py * DET + x2] = accP2[k] * m;
    }
}

extern "C" void kernel_launch(void* const* d_in, const int* in_sizes, int n_in,
                              void* d_out, int out_size)
{
    const float* x = (const float*)d_in[0];
    float* out = (float*)d_out;

    dim3 gf(NB, 12);          // 16 batches x ceil(180/16) angle tiles
    filter_kernel<<<gf, 512>>>(x);

    dim3 gr(NB, NPH);         // pack pair-columns once per (batch, phase)
    repack_kernel<<<gr, 256>>>();

    dim3 gb(8, 8, NB);        // 8 x-tiles (left half, mirrored) x 8 y-tiles
    backproj_kernel<<<gb, 256>>>(out);
}

// round 10
// speedup vs baseline: 1.3254x; 1.0950x over previous
#include <cuda_runtime.h>
#include <cuda_fp16.h>
#include <math.h>

#define DET 512
#define NB  16
#define NT  180
#define NPH 90
#define CW  768   // padded column width: detector index range [-128, 640)

// filtered sinogram, layout [b][t][d]
static __device__ float g_xf[(size_t)NB * NT * DET];
// packed pair-columns: [b][ph][i] = (half2(g_t,g_u), half2(d_t,d_u)), i in [0,768)
static __device__ uint2 g_pk[(size_t)NB * NPH * CW];

// bit-cast helpers (register moves only)
__device__ __forceinline__ unsigned int h2_to_u32(__half2 h) {
    return *reinterpret_cast<unsigned int*>(&h);
}
__device__ __forceinline__ __half2 u32_to_h2(unsigned int u) {
    return *reinterpret_cast<__half2*>(&u);
}

// ---------------------------------------------------------------------------
// Kernel 1: Ram-Lak filtering as direct convolution with closed-form kernel.
// Angle tile = 8 -> 368 blocks for occupancy (was 192 at 33% occ).
// ---------------------------------------------------------------------------
__global__ __launch_bounds__(512) void filter_kernel(const float* __restrict__ x)
{
    const int b  = blockIdx.x;
    const int t0 = blockIdx.y * 8;
    const int tid = threadIdx.x;            // 0..511

    __shared__ __align__(16) float xs[DET][8];    // x[b][m][t0..t0+7]
    __shared__ float Gt[DET];

    {
        int k = tid;
        float v;
        if (k == 0)       v = 0.5f;
        else if (k & 1) { float fk = (float)k; v = -2.0f / (9.869604401089358f * fk * fk); }
        else              v = 0.0f;
        Gt[k] = v;
    }

    const float* xb = x + (size_t)b * DET * NT;
    const int tt = tid & 7;
    const int mb = tid >> 3;                 // 0..63
    const int tg0 = t0 + tt;
    #pragma unroll
    for (int p = 0; p < 8; p++) {
        int m = mb + p * 64;
        xs[m][tt] = (tg0 < NT) ? xb[m * NT + tg0] : 0.0f;
    }
    __syncthreads();

    const int d = tid;
    float4 acc[2];
    {
        const float4* xd = (const float4*)xs[d];
        #pragma unroll
        for (int q = 0; q < 2; q++) {
            float4 v = xd[q];
            acc[q].x = 0.5f * v.x; acc[q].y = 0.5f * v.y;
            acc[q].z = 0.5f * v.z; acc[q].w = 0.5f * v.w;
        }
    }

    const int m0 = (d & 1) ^ 1;              // opposite parity of d
    for (int j = 0; j < 256; j++) {
        int m = m0 + 2 * j;
        int k = d - m; k = (k < 0) ? -k : k;
        float gv = Gt[k];
        const float4* xm = (const float4*)xs[m];
        #pragma unroll
        for (int q = 0; q < 2; q++) {
            float4 v = xm[q];
            acc[q].x = fmaf(gv, v.x, acc[q].x);
            acc[q].y = fmaf(gv, v.y, acc[q].y);
            acc[q].z = fmaf(gv, v.z, acc[q].z);
            acc[q].w = fmaf(gv, v.w, acc[q].w);
        }
    }

    float vals[8];
    #pragma unroll
    for (int q = 0; q < 2; q++) {
        vals[q*4+0] = acc[q].x; vals[q*4+1] = acc[q].y;
        vals[q*4+2] = acc[q].z; vals[q*4+3] = acc[q].w;
    }
    #pragma unroll
    for (int r = 0; r < 8; r++) {
        int tg = t0 + r;
        if (tg < NT) g_xf[((size_t)b * NT + tg) * DET + d] = vals[r];
    }
}

// ---------------------------------------------------------------------------
// Kernel 1b: repack into padded, fp16-packed pair-columns (transposed pack:
// .x = (g_t, g_u), .y = (d_t, d_u) so one HFMA2 serves both angles).
// ph=0 -> angles {0, 90}; ph in 1..89 -> angles {ph, 180-ph}.
// Entry i covers detector index d = i-128. Pads are zero; d=-1 is (0, g0)
// and d=511 is (g511, -g511), reproducing exact reference edge masking.
// ---------------------------------------------------------------------------
__global__ __launch_bounds__(256) void repack_kernel()
{
    const int b  = blockIdx.x;
    const int ph = blockIdx.y;
    const int t = (ph == 0) ? 0  : ph;
    const int u = (ph == 0) ? 90 : (180 - ph);

    const float* st = g_xf + ((size_t)b * NT + t) * DET;
    const float* su = g_xf + ((size_t)b * NT + u) * DET;
    uint2* dst = g_pk + ((size_t)b * NPH + ph) * CW;

    for (int i = threadIdx.x; i < CW; i += 256) {
        int d = i - 128;
        float gt = 0.0f, dt = 0.0f, gu = 0.0f, du = 0.0f;
        if (d >= 0 && d < DET) {
            gt = st[d]; dt = ((d < DET - 1) ? st[d + 1] : 0.0f) - gt;
            gu = su[d]; du = ((d < DET - 1) ? su[d + 1] : 0.0f) - gu;
        } else if (d == -1) {
            dt = st[0]; du = su[0];
        }
        uint2 e;
        e.x = h2_to_u32(__floats2half2_rn(gt, gu));   // (g_t, g_u)
        e.y = h2_to_u32(__floats2half2_rn(dt, du));   // (d_t, d_u)
        dst[i] = e;
    }
}

// ---------------------------------------------------------------------------
// Kernel 2: backprojection, mirror-angle pairing, fp16 packed columns.
// One LDS.64 + one HFMA2 per detector index computes BOTH angles' taps.
// ---------------------------------------------------------------------------
#define TAPIDX(iy, i0, w)                                    \
    {   float _tm = __fadd_rd((iy), MAGIC);                  \
        (i0) = __float_as_int(_tm) & 0x3FF;                  \
        (w)  = (iy) - (_tm - MAGIC); }

__global__ __launch_bounds__(256, 7) void backproj_kernel(float* __restrict__ out)
{
    const int b  = blockIdx.z;
    const int x0 = blockIdx.x * 32;          // left-half x tile [x0, x0+32)
    const int y0 = blockIdx.y * 64;          // y tile [y0, y0+64)
    const int tid = threadIdx.x;             // 0..255
    const int tx = tid & 31;
    const int ty = tid >> 5;                 // 0..7

    __shared__ __align__(16) uint2 col[2][CW];
    __shared__ float2 cs[NT];

    if (tid < NT) {
        float rad = (float)tid * 0.017453292519943295f;
        float sv, cv;
        sincosf(rad, &sv, &cv);
        cs[tid] = make_float2(cv, sv);
    }

    const uint2* pkb = g_pk + (size_t)b * NPH * CW;

    // preload phase 0
    #pragma unroll
    for (int r = 0; r < 3; r++) col[0][tid + r * 256] = pkb[tid + r * 256];
    __syncthreads();

    float accP1[8], accP2[8];
    #pragma unroll
    for (int k = 0; k < 8; k++) { accP1[k] = 0.0f; accP2[k] = 0.0f; }

    const float fx = (float)(x0 + tx) - 255.5f;        // < 0 always
    const float fy = (float)(y0 + ty) - 255.5f;
    const float lim = 65408.0f;                        // (1 - 1/512) * 256^2
    const float MAGIC = 8388608.0f;                    // 2^23

    const float fxmin = 255.5f - (float)(x0 + 31);
    float fymin;
    {
        float lo = fy, hi = fy + 56.0f;
        fymin = (lo <= 0.0f && hi >= 0.0f) ? 0.0f : fminf(fabsf(lo), fabsf(hi));
    }
    const bool active = (fxmin * fxmin + fymin * fymin) <= lim;  // warp-uniform

    for (int ph = 0; ph < NPH; ph++) {
        const int cur = ph & 1;
        // prefetch next phase (ph=89 re-reads phase 89: valid, unused)
        {
            const uint2* src = pkb + (size_t)((ph + 1 < NPH) ? ph + 1 : ph) * CW;
            uint2* dstc = col[cur ^ 1];
            #pragma unroll
            for (int r = 0; r < 3; r++) dstc[tid + r * 256] = src[tid + r * 256];
        }

        if (active) {
            const uint2* cp = col[cur];
            if (ph == 0) {
                // angles 0 (low lane) and 90 (high lane): 4 independent lookups
                const float2 a0 = cs[0];
                const float2 a9 = cs[90];
                #pragma unroll
                for (int k = 0; k < 8; k++) {
                    float fyk = fy + 8.0f * (float)k;
                    float b0 = fmaf(-a0.y, fyk, 383.5f);
                    float b9 = fmaf(-a9.y, fyk, 383.5f);
                    float iy, w; int i0; uint2 q; __half2 v;
                    iy = fmaf(a0.x,  fx, b0); TAPIDX(iy, i0, w); q = cp[i0];
                    v = __hfma2(__float2half2_rn(w), u32_to_h2(q.y), u32_to_h2(q.x));
                    accP1[k] += __low2float(v);
                    iy = fmaf(a0.x, -fx, b0); TAPIDX(iy, i0, w); q = cp[i0];
                    v = __hfma2(__float2half2_rn(w), u32_to_h2(q.y), u32_to_h2(q.x));
                    accP2[k] += __low2float(v);
                    iy = fmaf(a9.x,  fx, b9); TAPIDX(iy, i0, w); q = cp[i0];
                    v = __hfma2(__float2half2_rn(w), u32_to_h2(q.y), u32_to_h2(q.x));
                    accP1[k] += __high2float(v);
                    iy = fmaf(a9.x, -fx, b9); TAPIDX(iy, i0, w); q = cp[i0];
                    v = __hfma2(__float2half2_rn(w), u32_to_h2(q.y), u32_to_h2(q.x));
                    accP2[k] += __high2float(v);
                }
            } else {
                // pair (t=ph, u=180-ph): c_u = -c, s_u = s
                const float2 cst = cs[ph];
                const float c = cst.x, s = cst.y;
                const float iyA0 = fmaf(c, fx, fmaf(-s, fy, 383.5f));
                const float D    = -2.0f * (c * fx);      // iyB = iyA + D
                const float s8   = 8.0f * s;
                #pragma unroll
                for (int k = 0; k < 8; k++) {
                    float iyA = fmaf(-s8, (float)k, iyA0);
                    float iyB = iyA + D;
                    float w; int i0; uint2 q; __half2 v;
                    TAPIDX(iyA, i0, w); q = cp[i0];
                    v = __hfma2(__float2half2_rn(w), u32_to_h2(q.y), u32_to_h2(q.x));
                    accP1[k] += __low2float(v);    // (p1, t)
                    accP2[k] += __high2float(v);   // (p2, u)
                    TAPIDX(iyB, i0, w); q = cp[i0];
                    v = __hfma2(__float2half2_rn(w), u32_to_h2(q.y), u32_to_h2(q.x));
                    accP1[k] += __high2float(v);   // (p1, u)
                    accP2[k] += __low2float(v);    // (p2, t)
                }
            }
        }
        __syncthreads();
    }

    // epilogue: circle mask (mirror-exact) + pi/(2*180) scale
    const float scale = 0.008726646259971648f;   // pi/360
    float* ob = out + (size_t)b * DET * DET;
    const int x1 = x0 + tx;
    const int x2 = 511 - x1;
    #pragma unroll
    for (int k = 0; k < 8; k++) {
        int   py  = y0 + ty + 8 * k;
        float fyk = fy + 8.0f * (float)k;
        float m   = ((fx * fx + fyk * fyk) <= lim) ? scale : 0.0f;
        ob[(size_t)py * DET + x1] = accP1[k] * m;
        ob[(size_t)py * DET + x2] = accP2[k] * m;
    }
}

extern "C" void kernel_launch(void* const* d_in, const int* in_sizes, int n_in,
                              void* d_out, int out_size)
{
    const float* x = (const float*)d_in[0];
    float* out = (float*)d_out;

    dim3 gf(NB, 23);          // 16 batches x ceil(180/8) angle tiles
    filter_kernel<<<gf, 512>>>(x);

    dim3 gr(NB, NPH);         // pack pair-columns once per (batch, phase)
    repack_kernel<<<gr, 256>>>();

    dim3 gb(8, 8, NB);        // 8 x-tiles (left half, mirrored) x 8 y-tiles
    backproj_kernel<<<gb, 256>>>(out);
}